// round 1
// baseline (speedup 1.0000x reference)
#include <cuda_runtime.h>

// CIN cross-network: B=16384, M=32, D=16, layers H=64,64,64.
// out[b, L*64+k] = sum_d relu( sum_{m,h} x0[b,m,d]*xk[b,h,d]*W_L[m,h,k] )
//
// Block = 256 threads, handles TB=8 batch rows end-to-end (all 3 layers),
// xk state kept in shared memory. Inner contraction uses packed fp32
// (fma.rn.f32x2) over the d dimension.

#define TB      8
#define THREADS 256
#define PCH     64   // p-chunk: (m,h) pairs staged per iteration

typedef unsigned long long u64;

__device__ __forceinline__ u64 dup2(float w) {
    u64 r;
    asm("mov.b64 %0, {%1, %1};" : "=l"(r) : "f"(w));
    return r;
}
__device__ __forceinline__ void fma2(u64 &acc, u64 a, u64 b) {
    asm("fma.rn.f32x2 %0, %1, %2, %0;" : "+l"(acc) : "l"(a), "l"(b));
}
__device__ __forceinline__ void unpack2(u64 v, float &lo, float &hi) {
    asm("mov.b64 {%0, %1}, %2;" : "=f"(lo), "=f"(hi) : "l"(v));
}

__global__ void __launch_bounds__(THREADS, 2)
cin_kernel(const float* __restrict__ emb,
           const float* __restrict__ W0,
           const float* __restrict__ W1,
           const float* __restrict__ W2,
           float* __restrict__ out)
{
    extern __shared__ float smem[];
    float* X0s  = smem;              // TB*32*16 = 4096 floats
    float* Xks  = X0s  + TB * 512;   // TB*64*16 = 8192 floats
    float* zbuf = Xks  + TB * 1024;  // TB*64*16 = 8192 floats
    float* Wbuf = zbuf + TB * 1024;  // 64*64    = 4096 floats
    // total 24576 floats = 96 KB

    const int tid = threadIdx.x;
    const int b   = tid >> 5;   // warp == one batch row (uniform per warp)
    const int kt  = tid & 31;   // owns output columns k = 2*kt, 2*kt+1
    const long long bg0 = (long long)blockIdx.x * TB;

    // ---- load x0 for TB rows (TB*512 floats, coalesced float4) ----
    {
        const float4* g = (const float4*)(emb + bg0 * 512);
        float4* s = (float4*)X0s;
#pragma unroll
        for (int i = 0; i < 4; i++) s[tid + i * THREADS] = g[tid + i * THREADS];
    }
    __syncthreads();
    // ---- xk = x0 (first 32 rows of each 64-row slot) ----
    {
        const float4* s0 = (const float4*)X0s;
        float4* sk = (float4*)Xks;
#pragma unroll
        for (int i = 0; i < 4; i++) {
            int idx = tid + i * THREADS;       // 0..1023 (float4 units)
            int bb = idx >> 7, rr = idx & 127; // 128 float4 per b
            sk[bb * 256 + rr] = s0[idx];
        }
    }

    float* outb = out + (bg0 + b) * 192;

    for (int L = 0; L < 3; ++L) {
        const float* W = (L == 0) ? W0 : ((L == 1) ? W1 : W2);
        const int hsh    = (L == 0) ? 5 : 6;    // log2(H_in)
        const int nchunk = (L == 0) ? 16 : 32;  // P / PCH

        u64 accA[8], accB[8];
#pragma unroll
        for (int j = 0; j < 8; j++) { accA[j] = 0ull; accB[j] = 0ull; }

        for (int c = 0; c < nchunk; ++c) {
            __syncthreads();  // Wbuf/zbuf rewrite vs previous chunk's reads,
                              // and Xks writeback vs this layer's z-gen reads
            // ---- stage W chunk: 64 p-rows x 64 k = 4096 floats ----
            {
                const float4* g = (const float4*)(W + (c << 12));
                float4* s = (float4*)Wbuf;
#pragma unroll
                for (int i = 0; i < 4; i++)
                    s[tid + i * THREADS] = g[tid + i * THREADS];
            }
            // ---- z-gen: z[b][p][d] = x0[b][m][d] * xk[b][h][d] ----
#pragma unroll
            for (int i = 0; i < 2; i++) {
                int q  = tid + i * THREADS;     // 0..511 => (b, p)
                int zb = q >> 6, zp = q & 63;
                int pg = (c << 6) + zp;
                int m  = pg >> hsh;
                int h  = pg & ((1 << hsh) - 1);
                const float4* xr = (const float4*)(X0s + zb * 512 + m * 16);
                const float4* kr = (const float4*)(Xks + zb * 1024 + h * 16);
                float4* zr = (float4*)(zbuf + zb * 1024 + zp * 16);
#pragma unroll
                for (int j = 0; j < 4; j++) {
                    float4 a = xr[j], x = kr[j];
                    zr[j] = make_float4(a.x * x.x, a.y * x.y, a.z * x.z, a.w * x.w);
                }
            }
            __syncthreads();
            // ---- FMA phase: acc[k][d-pair] += z[p][d-pair] * W[p][k] ----
            const u64*    zrow = (const u64*)(zbuf + b * 1024);   // uniform per warp
            const float2* wrow = ((const float2*)Wbuf) + kt;      // p*32 + kt
#pragma unroll 4
            for (int p = 0; p < PCH; ++p) {
                float2 wv = wrow[p * 32];
                u64 wa = dup2(wv.x), wb = dup2(wv.y);
                const u64* z = zrow + p * 8;
#pragma unroll
                for (int j = 0; j < 8; j++) {
                    u64 zj = z[j];
                    fma2(accA[j], zj, wa);
                    fma2(accB[j], zj, wb);
                }
            }
        }
        __syncthreads();
        // ---- relu, write next xk, reduce over d, store output ----
        float sA = 0.f, sB = 0.f;
        float* xkA = Xks + b * 1024 + (2 * kt) * 16;
        float* xkB = xkA + 16;
#pragma unroll
        for (int j = 0; j < 8; j++) {
            float lo, hi;
            unpack2(accA[j], lo, hi);
            lo = fmaxf(lo, 0.f); hi = fmaxf(hi, 0.f);
            xkA[2 * j] = lo; xkA[2 * j + 1] = hi;
            sA += lo + hi;
            unpack2(accB[j], lo, hi);
            lo = fmaxf(lo, 0.f); hi = fmaxf(hi, 0.f);
            xkB[2 * j] = lo; xkB[2 * j + 1] = hi;
            sB += lo + hi;
        }
        ((float2*)(outb + L * 64))[kt] = make_float2(sA, sB);
    }
}

extern "C" void kernel_launch(void* const* d_in, const int* in_sizes, int n_in,
                              void* d_out, int out_size)
{
    const float* emb = (const float*)d_in[0];
    const float* W0  = (const float*)d_in[1];
    const float* W1  = (const float*)d_in[2];
    const float* W2  = (const float*)d_in[3];
    float* out = (float*)d_out;

    const int smem_bytes = 24576 * sizeof(float);  // 96 KB
    cudaFuncSetAttribute(cin_kernel,
                         cudaFuncAttributeMaxDynamicSharedMemorySize, smem_bytes);
    cin_kernel<<<16384 / TB, THREADS, smem_bytes>>>(emb, W0, W1, W2, out);
}

// round 3
// speedup vs baseline: 1.1547x; 1.1547x over previous
#include <cuda_runtime.h>

// CIN cross-network: B=16384, M=32, D=16, layers H=64,64,64.
// out[b, L*64+k] = sum_d relu( sum_{m,h} x0[b,m,d]*xk[b,h,d]*W_L[m,h,k] )
//
// Block = 256 threads = 8 warps; warp <-> one batch row for the FMA phase.
// Register tile per thread: 4 k-columns x 4 d-pairs (16 f32x2 accumulators).
// All smem traffic in the hot loop is LDS.128 with broadcast-friendly
// addressing: ~4 crossbar wavefronts per p per warp (vs 10 in R1).

#define TB      8
#define THREADS 256
#define PCH     64   // (m,h) pairs staged per iteration

typedef unsigned long long u64;

__device__ __forceinline__ u64 dup2(float w) {
    u64 r;
    asm("mov.b64 %0, {%1, %1};" : "=l"(r) : "f"(w));
    return r;
}
__device__ __forceinline__ void fma2(u64 &acc, u64 a, u64 b) {
    asm("fma.rn.f32x2 %0, %1, %2, %0;" : "+l"(acc) : "l"(a), "l"(b));
}
__device__ __forceinline__ void unpack2(u64 v, float &lo, float &hi) {
    asm("mov.b64 {%0, %1}, %2;" : "=f"(lo), "=f"(hi) : "l"(v));
}

__global__ void __launch_bounds__(THREADS, 2)
cin_kernel(const float* __restrict__ emb,
           const float* __restrict__ W0,
           const float* __restrict__ W1,
           const float* __restrict__ W2,
           float* __restrict__ out)
{
    extern __shared__ float smem[];
    float* X0s  = smem;              // TB*32*16 = 4096 floats
    float* Xks  = X0s  + TB * 512;   // TB*64*16 = 8192 floats
    float* zbuf = Xks  + TB * 1024;  // TB*64*16 = 8192 floats
    float* Wbuf = zbuf + TB * 1024;  // 64*64    = 4096 floats
    // total 24576 floats = 96 KB

    const int tid = threadIdx.x;
    const int b   = tid >> 5;        // warp == one batch row
    const int lane = tid & 31;
    const int kg  = lane & 15;       // k-group: owns k = kg*4 .. kg*4+3
    const int dg  = lane >> 4;       // d-group: owns d = dg*8 .. dg*8+7 (4 d-pairs)
    const long long bg0 = (long long)blockIdx.x * TB;

    // ---- load x0 for TB rows (coalesced float4) ----
    {
        const float4* g = (const float4*)(emb + bg0 * 512);
        float4* s = (float4*)X0s;
#pragma unroll
        for (int i = 0; i < 4; i++) s[tid + i * THREADS] = g[tid + i * THREADS];
    }
    __syncthreads();
    // ---- xk = x0 (first 32 rows of each 64-row slot) ----
    {
        const float4* s0 = (const float4*)X0s;
        float4* sk = (float4*)Xks;
#pragma unroll
        for (int i = 0; i < 4; i++) {
            int idx = tid + i * THREADS;       // 0..1023 (float4 units)
            int bb = idx >> 7, rr = idx & 127; // 128 float4 per b
            sk[bb * 256 + rr] = s0[idx];
        }
    }

    float* outb = out + (bg0 + b) * 192;

    for (int L = 0; L < 3; ++L) {
        const float* W = (L == 0) ? W0 : ((L == 1) ? W1 : W2);
        const int hsh    = (L == 0) ? 5 : 6;    // log2(H_in)
        const int nchunk = (L == 0) ? 16 : 32;  // P / PCH

        u64 acc[4][4];
#pragma unroll
        for (int i = 0; i < 4; i++)
#pragma unroll
            for (int j = 0; j < 4; j++) acc[i][j] = 0ull;

        for (int c = 0; c < nchunk; ++c) {
            __syncthreads();  // Wbuf/zbuf rewrite vs previous chunk's reads
            // ---- stage W chunk: 64 p-rows x 64 k = 4096 floats ----
            {
                const float4* g = (const float4*)(W + (c << 12));
                float4* s = (float4*)Wbuf;
#pragma unroll
                for (int i = 0; i < 4; i++)
                    s[tid + i * THREADS] = g[tid + i * THREADS];
            }
            // ---- z-gen: z[b][p][d] = x0[b][m][d] * xk[b][h][d] ----
#pragma unroll
            for (int i = 0; i < 2; i++) {
                int q  = tid + i * THREADS;     // 0..511 => (b, p)
                int zb = q >> 6, zp = q & 63;
                int pg = (c << 6) + zp;
                int m  = pg >> hsh;
                int h  = pg & ((1 << hsh) - 1);
                const float4* xr = (const float4*)(X0s + zb * 512 + m * 16);
                const float4* kr = (const float4*)(Xks + zb * 1024 + h * 16);
                float4* zr = (float4*)(zbuf + zb * 1024 + zp * 16);
#pragma unroll
                for (int j = 0; j < 4; j++) {
                    float4 a = xr[j], x = kr[j];
                    zr[j] = make_float4(a.x * x.x, a.y * x.y, a.z * x.z, a.w * x.w);
                }
            }
            __syncthreads();
            // ---- FMA phase: acc[k][dpair] += z[p][dpair] * W[p][k] ----
            // z row p lives at zbuf + b*1024 + p*16 floats = 4 ulonglong2 units
            const ulonglong2* zp2 = (const ulonglong2*)(zbuf + b * 1024 + dg * 8);
            const float4*     wp4 = ((const float4*)Wbuf) + kg;
#pragma unroll 8
            for (int p = 0; p < PCH; ++p) {
                float4 w = wp4[p * 16];
                ulonglong2 zA = zp2[p * 4];        // d = dg*8 + 0..3
                ulonglong2 zB = zp2[p * 4 + 1];    // d = dg*8 + 4..7
                u64 w0 = dup2(w.x), w1 = dup2(w.y), w2 = dup2(w.z), w3 = dup2(w.w);
                fma2(acc[0][0], zA.x, w0); fma2(acc[0][1], zA.y, w0);
                fma2(acc[0][2], zB.x, w0); fma2(acc[0][3], zB.y, w0);
                fma2(acc[1][0], zA.x, w1); fma2(acc[1][1], zA.y, w1);
                fma2(acc[1][2], zB.x, w1); fma2(acc[1][3], zB.y, w1);
                fma2(acc[2][0], zA.x, w2); fma2(acc[2][1], zA.y, w2);
                fma2(acc[2][2], zB.x, w2); fma2(acc[2][3], zB.y, w2);
                fma2(acc[3][0], zA.x, w3); fma2(acc[3][1], zA.y, w3);
                fma2(acc[3][2], zB.x, w3); fma2(acc[3][3], zB.y, w3);
            }
        }
        __syncthreads();
        // ---- relu, write next xk, reduce over d, store output ----
        float s[4];
#pragma unroll
        for (int i = 0; i < 4; i++) {
            float sum = 0.f;
            float2 v[4];
#pragma unroll
            for (int j = 0; j < 4; j++) {
                float lo, hi;
                unpack2(acc[i][j], lo, hi);
                lo = fmaxf(lo, 0.f); hi = fmaxf(hi, 0.f);
                sum += lo + hi;
                v[j] = make_float2(lo, hi);
            }
            float* xk = Xks + b * 1024 + (kg * 4 + i) * 16 + dg * 8;
            ((float4*)xk)[0] = make_float4(v[0].x, v[0].y, v[1].x, v[1].y);
            ((float4*)xk)[1] = make_float4(v[2].x, v[2].y, v[3].x, v[3].y);
            s[i] = sum;
        }
#pragma unroll
        for (int i = 0; i < 4; i++)
            s[i] += __shfl_xor_sync(0xffffffffu, s[i], 16);
        if (dg == 0)
            ((float4*)(outb + L * 64))[kg] = make_float4(s[0], s[1], s[2], s[3]);
    }
}

extern "C" void kernel_launch(void* const* d_in, const int* in_sizes, int n_in,
                              void* d_out, int out_size)
{
    const float* emb = (const float*)d_in[0];
    const float* W0  = (const float*)d_in[1];
    const float* W1  = (const float*)d_in[2];
    const float* W2  = (const float*)d_in[3];
    float* out = (float*)d_out;

    const int smem_bytes = 24576 * sizeof(float);  // 96 KB
    cudaFuncSetAttribute(cin_kernel,
                         cudaFuncAttributeMaxDynamicSharedMemorySize, smem_bytes);
    cin_kernel<<<16384 / TB, THREADS, smem_bytes>>>(emb, W0, W1, W2, out);
}

// round 4
// speedup vs baseline: 1.1561x; 1.0012x over previous
#include <cuda_runtime.h>

// CIN cross-network: B=16384, M=32, D=16, layers H=64,64,64.
// out[b, L*64+k] = sum_d relu( sum_{m,h} x0[b,m,d]*xk[b,h,d]*W_L[m,h,k] )
//
// Block = 256 threads = 8 warps; warp <-> one batch row for the FMA phase.
// Register tile per thread: 4 k-columns x 4 d-pairs (16 f32x2 accumulators).
// All smem traffic in the hot loop is LDS.128 with broadcast-friendly
// addressing: ~4 crossbar wavefronts per p per warp (vs 10 in R1).

#define TB      8
#define THREADS 256
#define PCH     64   // (m,h) pairs staged per iteration

typedef unsigned long long u64;

__device__ __forceinline__ u64 dup2(float w) {
    u64 r;
    asm("mov.b64 %0, {%1, %1};" : "=l"(r) : "f"(w));
    return r;
}
__device__ __forceinline__ void fma2(u64 &acc, u64 a, u64 b) {
    asm("fma.rn.f32x2 %0, %1, %2, %0;" : "+l"(acc) : "l"(a), "l"(b));
}
__device__ __forceinline__ void unpack2(u64 v, float &lo, float &hi) {
    asm("mov.b64 {%0, %1}, %2;" : "=f"(lo), "=f"(hi) : "l"(v));
}

__global__ void __launch_bounds__(THREADS, 2)
cin_kernel(const float* __restrict__ emb,
           const float* __restrict__ W0,
           const float* __restrict__ W1,
           const float* __restrict__ W2,
           float* __restrict__ out)
{
    extern __shared__ float smem[];
    float* X0s  = smem;              // TB*32*16 = 4096 floats
    float* Xks  = X0s  + TB * 512;   // TB*64*16 = 8192 floats
    float* zbuf = Xks  + TB * 1024;  // TB*64*16 = 8192 floats
    float* Wbuf = zbuf + TB * 1024;  // 64*64    = 4096 floats
    // total 24576 floats = 96 KB

    const int tid = threadIdx.x;
    const int b   = tid >> 5;        // warp == one batch row
    const int lane = tid & 31;
    const int kg  = lane & 15;       // k-group: owns k = kg*4 .. kg*4+3
    const int dg  = lane >> 4;       // d-group: owns d = dg*8 .. dg*8+7 (4 d-pairs)
    const long long bg0 = (long long)blockIdx.x * TB;

    // ---- load x0 for TB rows (coalesced float4) ----
    {
        const float4* g = (const float4*)(emb + bg0 * 512);
        float4* s = (float4*)X0s;
#pragma unroll
        for (int i = 0; i < 4; i++) s[tid + i * THREADS] = g[tid + i * THREADS];
    }
    __syncthreads();
    // ---- xk = x0 (first 32 rows of each 64-row slot) ----
    {
        const float4* s0 = (const float4*)X0s;
        float4* sk = (float4*)Xks;
#pragma unroll
        for (int i = 0; i < 4; i++) {
            int idx = tid + i * THREADS;       // 0..1023 (float4 units)
            int bb = idx >> 7, rr = idx & 127; // 128 float4 per b
            sk[bb * 256 + rr] = s0[idx];
        }
    }

    float* outb = out + (bg0 + b) * 192;

    for (int L = 0; L < 3; ++L) {
        const float* W = (L == 0) ? W0 : ((L == 1) ? W1 : W2);
        const int hsh    = (L == 0) ? 5 : 6;    // log2(H_in)
        const int nchunk = (L == 0) ? 16 : 32;  // P / PCH

        u64 acc[4][4];
#pragma unroll
        for (int i = 0; i < 4; i++)
#pragma unroll
            for (int j = 0; j < 4; j++) acc[i][j] = 0ull;

        for (int c = 0; c < nchunk; ++c) {
            __syncthreads();  // Wbuf/zbuf rewrite vs previous chunk's reads
            // ---- stage W chunk: 64 p-rows x 64 k = 4096 floats ----
            {
                const float4* g = (const float4*)(W + (c << 12));
                float4* s = (float4*)Wbuf;
#pragma unroll
                for (int i = 0; i < 4; i++)
                    s[tid + i * THREADS] = g[tid + i * THREADS];
            }
            // ---- z-gen: z[b][p][d] = x0[b][m][d] * xk[b][h][d] ----
#pragma unroll
            for (int i = 0; i < 2; i++) {
                int q  = tid + i * THREADS;     // 0..511 => (b, p)
                int zb = q >> 6, zp = q & 63;
                int pg = (c << 6) + zp;
                int m  = pg >> hsh;
                int h  = pg & ((1 << hsh) - 1);
                const float4* xr = (const float4*)(X0s + zb * 512 + m * 16);
                const float4* kr = (const float4*)(Xks + zb * 1024 + h * 16);
                float4* zr = (float4*)(zbuf + zb * 1024 + zp * 16);
#pragma unroll
                for (int j = 0; j < 4; j++) {
                    float4 a = xr[j], x = kr[j];
                    zr[j] = make_float4(a.x * x.x, a.y * x.y, a.z * x.z, a.w * x.w);
                }
            }
            __syncthreads();
            // ---- FMA phase: acc[k][dpair] += z[p][dpair] * W[p][k] ----
            // z row p lives at zbuf + b*1024 + p*16 floats = 4 ulonglong2 units
            const ulonglong2* zp2 = (const ulonglong2*)(zbuf + b * 1024 + dg * 8);
            const float4*     wp4 = ((const float4*)Wbuf) + kg;
#pragma unroll 8
            for (int p = 0; p < PCH; ++p) {
                float4 w = wp4[p * 16];
                ulonglong2 zA = zp2[p * 4];        // d = dg*8 + 0..3
                ulonglong2 zB = zp2[p * 4 + 1];    // d = dg*8 + 4..7
                u64 w0 = dup2(w.x), w1 = dup2(w.y), w2 = dup2(w.z), w3 = dup2(w.w);
                fma2(acc[0][0], zA.x, w0); fma2(acc[0][1], zA.y, w0);
                fma2(acc[0][2], zB.x, w0); fma2(acc[0][3], zB.y, w0);
                fma2(acc[1][0], zA.x, w1); fma2(acc[1][1], zA.y, w1);
                fma2(acc[1][2], zB.x, w1); fma2(acc[1][3], zB.y, w1);
                fma2(acc[2][0], zA.x, w2); fma2(acc[2][1], zA.y, w2);
                fma2(acc[2][2], zB.x, w2); fma2(acc[2][3], zB.y, w2);
                fma2(acc[3][0], zA.x, w3); fma2(acc[3][1], zA.y, w3);
                fma2(acc[3][2], zB.x, w3); fma2(acc[3][3], zB.y, w3);
            }
        }
        __syncthreads();
        // ---- relu, write next xk, reduce over d, store output ----
        float s[4];
#pragma unroll
        for (int i = 0; i < 4; i++) {
            float sum = 0.f;
            float2 v[4];
#pragma unroll
            for (int j = 0; j < 4; j++) {
                float lo, hi;
                unpack2(acc[i][j], lo, hi);
                lo = fmaxf(lo, 0.f); hi = fmaxf(hi, 0.f);
                sum += lo + hi;
                v[j] = make_float2(lo, hi);
            }
            float* xk = Xks + b * 1024 + (kg * 4 + i) * 16 + dg * 8;
            ((float4*)xk)[0] = make_float4(v[0].x, v[0].y, v[1].x, v[1].y);
            ((float4*)xk)[1] = make_float4(v[2].x, v[2].y, v[3].x, v[3].y);
            s[i] = sum;
        }
#pragma unroll
        for (int i = 0; i < 4; i++)
            s[i] += __shfl_xor_sync(0xffffffffu, s[i], 16);
        if (dg == 0)
            ((float4*)(outb + L * 64))[kg] = make_float4(s[0], s[1], s[2], s[3]);
    }
}

extern "C" void kernel_launch(void* const* d_in, const int* in_sizes, int n_in,
                              void* d_out, int out_size)
{
    const float* emb = (const float*)d_in[0];
    const float* W0  = (const float*)d_in[1];
    const float* W1  = (const float*)d_in[2];
    const float* W2  = (const float*)d_in[3];
    float* out = (float*)d_out;

    const int smem_bytes = 24576 * sizeof(float);  // 96 KB
    cudaFuncSetAttribute(cin_kernel,
                         cudaFuncAttributeMaxDynamicSharedMemorySize, smem_bytes);
    cin_kernel<<<16384 / TB, THREADS, smem_bytes>>>(emb, W0, W1, W2, out);
}

// round 5
// speedup vs baseline: 1.3889x; 1.2013x over previous
#include <cuda_runtime.h>
#include <cstdint>

// CIN cross-network: B=16384, M=32, D=16, layers H=64,64,64.
// Two-stage: S_m[k,d] = sum_h xk[h,d]*W[m,h,k];  out[k,d] += x0[m,d]*S_m[k,d]
// Register tile: 4 m x 4 k x 4 d-pairs of f32x2 accumulators per thread.
// W streamed via cp.async.bulk (double-buffered), no z materialization.

#define THREADS 256
#define TB      8
#define NCHUNK  24

typedef unsigned long long u64;

// smem byte offsets
#define SM_MBAR  0
#define SM_X0    1024                 // 4096 floats (16 KB)
#define SM_XK    (SM_X0 + 16384)      // 8192 floats (32 KB)
#define SM_W     (SM_XK + 32768)      // 2 x 16384 floats (128 KB)
#define SM_TOTAL (SM_W + 131072)

__device__ __forceinline__ uint32_t smem_u32(const void* p) {
    uint32_t a;
    asm("{ .reg .u64 t; cvta.to.shared.u64 t, %1; cvt.u32.u64 %0, t; }"
        : "=r"(a) : "l"(p));
    return a;
}
__device__ __forceinline__ u64 dup2(float w) {
    u64 r;
    asm("mov.b64 %0, {%1, %1};" : "=l"(r) : "f"(w));
    return r;
}
__device__ __forceinline__ void fma2(u64 &acc, u64 a, u64 b) {
    asm("fma.rn.f32x2 %0, %1, %2, %0;" : "+l"(acc) : "l"(a), "l"(b));
}
__device__ __forceinline__ void unpack2(u64 v, float &lo, float &hi) {
    asm("mov.b64 {%0, %1}, %2;" : "=f"(lo), "=f"(hi) : "l"(v));
}
__device__ __forceinline__ void mbar_init(uint32_t m, uint32_t cnt) {
    asm volatile("mbarrier.init.shared.b64 [%0], %1;" :: "r"(m), "r"(cnt) : "memory");
}
__device__ __forceinline__ void mbar_expect_tx(uint32_t m, uint32_t bytes) {
    asm volatile("mbarrier.arrive.expect_tx.shared.b64 _, [%0], %1;"
                 :: "r"(m), "r"(bytes) : "memory");
}
__device__ __forceinline__ void bulk_g2s(uint32_t dst, const void* src,
                                         uint32_t bytes, uint32_t m) {
    asm volatile("cp.async.bulk.shared::cta.global.mbarrier::complete_tx::bytes "
                 "[%0], [%1], %2, [%3];"
                 :: "r"(dst), "l"(src), "r"(bytes), "r"(m) : "memory");
}
__device__ __forceinline__ void mbar_wait(uint32_t m, uint32_t parity) {
    asm volatile(
        "{\n\t.reg .pred P;\n\t"
        "W_%=:\n\t"
        "mbarrier.try_wait.parity.acquire.cta.shared::cta.b64 P, [%0], %1, 0x989680;\n\t"
        "@P bra D_%=;\n\t"
        "bra W_%=;\n\t"
        "D_%=:\n\t}"
        :: "r"(m), "r"(parity) : "memory");
}

__device__ __forceinline__ const float* chunk_ptr(
    const float* W0, const float* W1, const float* W2, int i, uint32_t& bytes)
{
    if (i < 8)  { bytes = 4u * 32 * 64 * 4; return W0 + (size_t)i * (4 * 32 * 64); }
    if (i < 16) { bytes = 4u * 64 * 64 * 4; return W1 + (size_t)(i - 8)  * (4 * 64 * 64); }
    bytes = 4u * 64 * 64 * 4; return W2 + (size_t)(i - 16) * (4 * 64 * 64);
}

__global__ void __launch_bounds__(THREADS, 1)
cin_kernel(const float* __restrict__ emb,
           const float* __restrict__ W0,
           const float* __restrict__ W1,
           const float* __restrict__ W2,
           float* __restrict__ out)
{
    extern __shared__ char smem[];
    float* X0s = (float*)(smem + SM_X0);
    float* Xks = (float*)(smem + SM_XK);
    float* Wb[2] = { (float*)(smem + SM_W), (float*)(smem + SM_W) + 16384 };
    const uint32_t mb0 = smem_u32(smem + SM_MBAR);
    const uint32_t mb1 = mb0 + 8;
    const uint32_t wsm[2] = { smem_u32(Wb[0]), smem_u32(Wb[1]) };

    const int tid  = threadIdx.x;
    const int b    = tid >> 5;       // warp == one batch row
    const int lane = tid & 31;
    const int kg   = lane & 15;      // k-quad: k = 4*kg .. 4*kg+3
    const int dg   = lane >> 4;      // d-half: dpairs dg*4 .. dg*4+3
    const long long bg0 = (long long)blockIdx.x * TB;

    if (tid == 0) { mbar_init(mb0, 1); mbar_init(mb1, 1); }

    // ---- load x0 for TB rows (coalesced float4) ----
    {
        const float4* g = (const float4*)(emb + bg0 * 512);
        float4* s = (float4*)X0s;
#pragma unroll
        for (int i = 0; i < 4; i++) s[tid + i * THREADS] = g[tid + i * THREADS];
    }
    __syncthreads();

    // prefetch chunk 0
    if (tid == 0) {
        uint32_t by; const float* p = chunk_ptr(W0, W1, W2, 0, by);
        mbar_expect_tx(mb0, by);
        bulk_g2s(wsm[0], p, by, mb0);
    }

    int ph[2] = { 0, 0 };
    int ci = 0;
    float* outb = out + (bg0 + b) * 192;

    for (int L = 0; L < 3; ++L) {
        const int Hin = L ? 64 : 32;
        const float* srcb = (L ? (Xks + b * 1024) : (X0s + b * 512)) + dg * 8;

        u64 o[4][4];
#pragma unroll
        for (int q = 0; q < 4; q++)
#pragma unroll
            for (int j = 0; j < 4; j++) o[q][j] = 0ull;

        for (int mc = 0; mc < 8; ++mc, ++ci) {
            const int buf = ci & 1;
            // prefetch next chunk into the other buffer (safe: its last
            // readers finished at the __syncthreads ending chunk ci-1)
            if (tid == 0 && ci + 1 < NCHUNK) {
                uint32_t by; const float* p = chunk_ptr(W0, W1, W2, ci + 1, by);
                mbar_expect_tx(buf ? mb0 : mb1, by);
                bulk_g2s(wsm[buf ^ 1], p, by, buf ? mb0 : mb1);
            }
            mbar_wait(buf ? mb1 : mb0, ph[buf]); ph[buf] ^= 1;
            const float* Wc = Wb[buf] + 4 * kg;

            u64 S[4][4][4];
#pragma unroll
            for (int mm = 0; mm < 4; mm++)
#pragma unroll
                for (int q = 0; q < 4; q++)
#pragma unroll
                    for (int j = 0; j < 4; j++) S[mm][q][j] = 0ull;

            for (int h = 0; h < Hin; ++h) {
                ulonglong2 za = *(const ulonglong2*)(srcb + h * 16);
                ulonglong2 zb = *(const ulonglong2*)(srcb + h * 16 + 4);
#pragma unroll
                for (int mm = 0; mm < 4; mm++) {
                    float4 w = *(const float4*)(Wc + (mm * Hin + h) * 64);
                    u64 w0 = dup2(w.x), w1 = dup2(w.y);
                    u64 w2 = dup2(w.z), w3 = dup2(w.w);
                    fma2(S[mm][0][0], za.x, w0); fma2(S[mm][0][1], za.y, w0);
                    fma2(S[mm][0][2], zb.x, w0); fma2(S[mm][0][3], zb.y, w0);
                    fma2(S[mm][1][0], za.x, w1); fma2(S[mm][1][1], za.y, w1);
                    fma2(S[mm][1][2], zb.x, w1); fma2(S[mm][1][3], zb.y, w1);
                    fma2(S[mm][2][0], za.x, w2); fma2(S[mm][2][1], za.y, w2);
                    fma2(S[mm][2][2], zb.x, w2); fma2(S[mm][2][3], zb.y, w2);
                    fma2(S[mm][3][0], za.x, w3); fma2(S[mm][3][1], za.y, w3);
                    fma2(S[mm][3][2], zb.x, w3); fma2(S[mm][3][3], zb.y, w3);
                }
            }
            // fold S_m into out with x0[m]
#pragma unroll
            for (int mm = 0; mm < 4; mm++) {
                const float* xp = X0s + b * 512 + (mc * 4 + mm) * 16 + dg * 8;
                ulonglong2 xa = *(const ulonglong2*)xp;
                ulonglong2 xb = *(const ulonglong2*)(xp + 4);
#pragma unroll
                for (int q = 0; q < 4; q++) {
                    fma2(o[q][0], S[mm][q][0], xa.x);
                    fma2(o[q][1], S[mm][q][1], xa.y);
                    fma2(o[q][2], S[mm][q][2], xb.x);
                    fma2(o[q][3], S[mm][q][3], xb.y);
                }
            }
            __syncthreads();  // everyone done with Wb[buf] before it is refilled
        }

        // ---- layer epilogue: relu, write next xk, d-reduce, store out ----
        float s[4];
#pragma unroll
        for (int q = 0; q < 4; q++) {
            float sum = 0.f;
            float2 v[4];
#pragma unroll
            for (int j = 0; j < 4; j++) {
                float lo, hi;
                unpack2(o[q][j], lo, hi);
                lo = fmaxf(lo, 0.f); hi = fmaxf(hi, 0.f);
                sum += lo + hi;
                v[j] = make_float2(lo, hi);
            }
            if (L < 2) {
                float* xw = Xks + b * 1024 + (4 * kg + q) * 16 + dg * 8;
                ((float4*)xw)[0] = make_float4(v[0].x, v[0].y, v[1].x, v[1].y);
                ((float4*)xw)[1] = make_float4(v[2].x, v[2].y, v[3].x, v[3].y);
            }
            s[q] = sum;
        }
#pragma unroll
        for (int q = 0; q < 4; q++)
            s[q] += __shfl_xor_sync(0xffffffffu, s[q], 16);
        if (dg == 0)
            ((float4*)(outb + L * 64))[kg] = make_float4(s[0], s[1], s[2], s[3]);
        // no cross-warp barrier needed: each warp reads/writes only its own
        // Xks row, and the next chunk's W-buffer sync is inside the mc loop
    }
}

extern "C" void kernel_launch(void* const* d_in, const int* in_sizes, int n_in,
                              void* d_out, int out_size)
{
    const float* emb = (const float*)d_in[0];
    const float* W0  = (const float*)d_in[1];
    const float* W1  = (const float*)d_in[2];
    const float* W2  = (const float*)d_in[3];
    float* out = (float*)d_out;

    cudaFuncSetAttribute(cin_kernel,
                         cudaFuncAttributeMaxDynamicSharedMemorySize, SM_TOTAL);
    cin_kernel<<<16384 / TB, THREADS, SM_TOTAL>>>(emb, W0, W1, W2, out);
}

// round 6
// speedup vs baseline: 1.4905x; 1.0732x over previous
#include <cuda_runtime.h>
#include <cstdint>

// CIN cross-network: B=16384, M=32, D=16, layers H=64,64,64.
// Two-stage per m: S[k,d] = sum_h xk[h,d]*W[m,h,k]; out[k,d] += x0[m,d]*S[k,d]
// Register tile: 1 m x 4 k x 4 d-pairs (16 f32x2 accs) -> ~100 regs,
// 2 blocks x 256 threads per SM (16 warps) to hide LDS latency.
// W streamed via cp.async.bulk, double-buffered, m=1 granularity.

#define THREADS 256
#define TB      8
#define NCHUNK  96

typedef unsigned long long u64;

// smem byte offsets
#define SM_MBAR  0
#define SM_X0    1024                  // 4096 floats (16 KB)
#define SM_XK    (SM_X0 + 16384)       // 8192 floats (32 KB)
#define SM_W     (SM_XK + 32768)       // 2 x 4096 floats (32 KB)
#define SM_TOTAL (SM_W + 32768)        // 81 KB

__device__ __forceinline__ uint32_t smem_u32(const void* p) {
    uint32_t a;
    asm("{ .reg .u64 t; cvta.to.shared.u64 t, %1; cvt.u32.u64 %0, t; }"
        : "=r"(a) : "l"(p));
    return a;
}
__device__ __forceinline__ u64 dup2(float w) {
    u64 r;
    asm("mov.b64 %0, {%1, %1};" : "=l"(r) : "f"(w));
    return r;
}
__device__ __forceinline__ void fma2(u64 &acc, u64 a, u64 b) {
    asm("fma.rn.f32x2 %0, %1, %2, %0;" : "+l"(acc) : "l"(a), "l"(b));
}
__device__ __forceinline__ void unpack2(u64 v, float &lo, float &hi) {
    asm("mov.b64 {%0, %1}, %2;" : "=f"(lo), "=f"(hi) : "l"(v));
}
__device__ __forceinline__ void mbar_init(uint32_t m, uint32_t cnt) {
    asm volatile("mbarrier.init.shared.b64 [%0], %1;" :: "r"(m), "r"(cnt) : "memory");
}
__device__ __forceinline__ void mbar_expect_tx(uint32_t m, uint32_t bytes) {
    asm volatile("mbarrier.arrive.expect_tx.shared.b64 _, [%0], %1;"
                 :: "r"(m), "r"(bytes) : "memory");
}
__device__ __forceinline__ void bulk_g2s(uint32_t dst, const void* src,
                                         uint32_t bytes, uint32_t m) {
    asm volatile("cp.async.bulk.shared::cta.global.mbarrier::complete_tx::bytes "
                 "[%0], [%1], %2, [%3];"
                 :: "r"(dst), "l"(src), "r"(bytes), "r"(m) : "memory");
}
__device__ __forceinline__ void mbar_wait(uint32_t m, uint32_t parity) {
    asm volatile(
        "{\n\t.reg .pred P;\n\t"
        "W_%=:\n\t"
        "mbarrier.try_wait.parity.acquire.cta.shared::cta.b64 P, [%0], %1, 0x989680;\n\t"
        "@P bra D_%=;\n\t"
        "bra W_%=;\n\t"
        "D_%=:\n\t}"
        :: "r"(m), "r"(parity) : "memory");
}

__device__ __forceinline__ const float* chunk_ptr(
    const float* W0, const float* W1, const float* W2, int i, uint32_t& bytes)
{
    if (i < 32) { bytes = 32u * 64 * 4; return W0 + (size_t)i * (32 * 64); }
    if (i < 64) { bytes = 64u * 64 * 4; return W1 + (size_t)(i - 32) * (64 * 64); }
    bytes = 64u * 64 * 4; return W2 + (size_t)(i - 64) * (64 * 64);
}

__global__ void __launch_bounds__(THREADS, 2)
cin_kernel(const float* __restrict__ emb,
           const float* __restrict__ W0,
           const float* __restrict__ W1,
           const float* __restrict__ W2,
           float* __restrict__ out)
{
    extern __shared__ char smem[];
    float* X0s = (float*)(smem + SM_X0);
    float* Xks = (float*)(smem + SM_XK);
    float* Wb[2] = { (float*)(smem + SM_W), (float*)(smem + SM_W) + 4096 };
    const uint32_t mb0 = smem_u32(smem + SM_MBAR);
    const uint32_t mb1 = mb0 + 8;
    const uint32_t wsm[2] = { smem_u32(Wb[0]), smem_u32(Wb[1]) };

    const int tid  = threadIdx.x;
    const int b    = tid >> 5;       // warp == one batch row
    const int lane = tid & 31;
    const int kg   = lane & 15;      // k-quad: k = 4*kg .. 4*kg+3
    const int dg   = lane >> 4;      // d-half: dpairs dg*4 .. dg*4+3
    const long long bg0 = (long long)blockIdx.x * TB;

    if (tid == 0) { mbar_init(mb0, 1); mbar_init(mb1, 1); }

    // ---- load x0 for TB rows (coalesced float4) ----
    {
        const float4* g = (const float4*)(emb + bg0 * 512);
        float4* s = (float4*)X0s;
#pragma unroll
        for (int i = 0; i < 4; i++) s[tid + i * THREADS] = g[tid + i * THREADS];
    }
    __syncthreads();

    // prefetch chunk 0
    if (tid == 0) {
        uint32_t by; const float* p = chunk_ptr(W0, W1, W2, 0, by);
        mbar_expect_tx(mb0, by);
        bulk_g2s(wsm[0], p, by, mb0);
    }

    int ph[2] = { 0, 0 };
    int ci = 0;
    float* outb = out + (bg0 + b) * 192;

    for (int L = 0; L < 3; ++L) {
        const int Hin = L ? 64 : 32;
        const float* srcb = (L ? (Xks + b * 1024) : (X0s + b * 512)) + dg * 8;

        u64 o[4][4];
#pragma unroll
        for (int q = 0; q < 4; q++)
#pragma unroll
            for (int j = 0; j < 4; j++) o[q][j] = 0ull;

        for (int mc = 0; mc < 32; ++mc, ++ci) {
            const int buf = ci & 1;
            // prefetch next chunk into the other buffer (its readers all
            // passed the __syncthreads that ended chunk ci-1)
            if (tid == 0 && ci + 1 < NCHUNK) {
                uint32_t by; const float* p = chunk_ptr(W0, W1, W2, ci + 1, by);
                mbar_expect_tx(buf ? mb0 : mb1, by);
                bulk_g2s(wsm[buf ^ 1], p, by, buf ? mb0 : mb1);
            }
            mbar_wait(buf ? mb1 : mb0, ph[buf]); ph[buf] ^= 1;
            const float* Wc = Wb[buf] + 4 * kg;

            u64 S[4][4];
#pragma unroll
            for (int q = 0; q < 4; q++)
#pragma unroll
                for (int j = 0; j < 4; j++) S[q][j] = 0ull;

#pragma unroll 8
            for (int h = 0; h < Hin; ++h) {
                ulonglong2 za = *(const ulonglong2*)(srcb + h * 16);
                ulonglong2 zb = *(const ulonglong2*)(srcb + h * 16 + 4);
                float4 w = *(const float4*)(Wc + h * 64);
                u64 w0 = dup2(w.x), w1 = dup2(w.y);
                u64 w2 = dup2(w.z), w3 = dup2(w.w);
                fma2(S[0][0], za.x, w0); fma2(S[0][1], za.y, w0);
                fma2(S[0][2], zb.x, w0); fma2(S[0][3], zb.y, w0);
                fma2(S[1][0], za.x, w1); fma2(S[1][1], za.y, w1);
                fma2(S[1][2], zb.x, w1); fma2(S[1][3], zb.y, w1);
                fma2(S[2][0], za.x, w2); fma2(S[2][1], za.y, w2);
                fma2(S[2][2], zb.x, w2); fma2(S[2][3], zb.y, w2);
                fma2(S[3][0], za.x, w3); fma2(S[3][1], za.y, w3);
                fma2(S[3][2], zb.x, w3); fma2(S[3][3], zb.y, w3);
            }
            // fold S into o with x0[mc]
            {
                const float* xp = X0s + b * 512 + mc * 16 + dg * 8;
                ulonglong2 xa = *(const ulonglong2*)xp;
                ulonglong2 xb = *(const ulonglong2*)(xp + 4);
#pragma unroll
                for (int q = 0; q < 4; q++) {
                    fma2(o[q][0], S[q][0], xa.x);
                    fma2(o[q][1], S[q][1], xa.y);
                    fma2(o[q][2], S[q][2], xb.x);
                    fma2(o[q][3], S[q][3], xb.y);
                }
            }
            __syncthreads();  // everyone done with Wb[buf] before it is refilled
        }

        // ---- layer epilogue: relu, write next xk, d-reduce, store out ----
        float s[4];
#pragma unroll
        for (int q = 0; q < 4; q++) {
            float sum = 0.f;
            float2 v[4];
#pragma unroll
            for (int j = 0; j < 4; j++) {
                float lo, hi;
                unpack2(o[q][j], lo, hi);
                lo = fmaxf(lo, 0.f); hi = fmaxf(hi, 0.f);
                sum += lo + hi;
                v[j] = make_float2(lo, hi);
            }
            if (L < 2) {
                float* xw = Xks + b * 1024 + (4 * kg + q) * 16 + dg * 8;
                ((float4*)xw)[0] = make_float4(v[0].x, v[0].y, v[1].x, v[1].y);
                ((float4*)xw)[1] = make_float4(v[2].x, v[2].y, v[3].x, v[3].y);
            }
            s[q] = sum;
        }
#pragma unroll
        for (int q = 0; q < 4; q++)
            s[q] += __shfl_xor_sync(0xffffffffu, s[q], 16);
        if (dg == 0)
            ((float4*)(outb + L * 64))[kg] = make_float4(s[0], s[1], s[2], s[3]);
        // no cross-warp barrier needed: each warp only touches its own Xks row
    }
}

extern "C" void kernel_launch(void* const* d_in, const int* in_sizes, int n_in,
                              void* d_out, int out_size)
{
    const float* emb = (const float*)d_in[0];
    const float* W0  = (const float*)d_in[1];
    const float* W1  = (const float*)d_in[2];
    const float* W2  = (const float*)d_in[3];
    float* out = (float*)d_out;

    cudaFuncSetAttribute(cin_kernel,
                         cudaFuncAttributeMaxDynamicSharedMemorySize, SM_TOTAL);
    cin_kernel<<<16384 / TB, THREADS, SM_TOTAL>>>(emb, W0, W1, W2, out);
}

// round 8
// speedup vs baseline: 2.9819x; 2.0006x over previous
#include <cuda_runtime.h>
#include <cstdint>

// CIN cross-network via warp-level HMMA (mma.sync m16n8k16 bf16, 3-pass
// hi/lo split) — tcgen05 unavailable (harness targets plain sm_103).
// Per block: 8 batch rows -> A rows r=(b*16+d)=128, N=64 outputs.
// Per m: P = xk*W_m on tensor cores; out += x0[:,m] (*) P in fp32.

#define THREADS 256
#define TB 8

// smem byte offsets
#define O_X0   0        // float[4096]              16384
#define O_XK   16384    // float[128*64]            32768
#define O_XFH  49152    // uint4[4*8*32]            16384
#define O_XFL  65536    // uint4[4*8*32]            16384
#define O_WF   81920    // uint2[2][2][4][8][32]    32768
#define SM_TOTAL 114688

__device__ __forceinline__ uint32_t cvt_bf16x2(float lo, float hi) {
    uint32_t r;
    asm("cvt.rn.satfinite.bf16x2.f32 %0, %1, %2;" : "=r"(r) : "f"(hi), "f"(lo));
    return r;
}
// split (a,b) fp32 -> packed bf16x2 hi (truncate) + bf16x2 lo (exact remainder)
__device__ __forceinline__ void split2(float a, float b, uint32_t& h, uint32_t& l) {
    uint32_t ua = __float_as_uint(a), ub = __float_as_uint(b);
    h = __byte_perm(ua, ub, 0x7632);
    float la = a - __uint_as_float(ua & 0xffff0000u);
    float lb = b - __uint_as_float(ub & 0xffff0000u);
    l = cvt_bf16x2(la, lb);
}
__device__ __forceinline__ void mma_zc(float d[4], const uint4& a, const uint2& b) {
    asm("mma.sync.aligned.m16n8k16.row.col.f32.bf16.bf16.f32 "
        "{%0,%1,%2,%3}, {%4,%5,%6,%7}, {%8,%9}, {%10,%11,%12,%13};"
        : "=f"(d[0]), "=f"(d[1]), "=f"(d[2]), "=f"(d[3])
        : "r"(a.x), "r"(a.y), "r"(a.z), "r"(a.w), "r"(b.x), "r"(b.y),
          "f"(0.f), "f"(0.f), "f"(0.f), "f"(0.f));
}
__device__ __forceinline__ void mma_acc(float d[4], const uint4& a, const uint2& b) {
    asm("mma.sync.aligned.m16n8k16.row.col.f32.bf16.bf16.f32 "
        "{%0,%1,%2,%3}, {%4,%5,%6,%7}, {%8,%9}, {%0,%1,%2,%3};"
        : "+f"(d[0]), "+f"(d[1]), "+f"(d[2]), "+f"(d[3])
        : "r"(a.x), "r"(a.y), "r"(a.z), "r"(a.w), "r"(b.x), "r"(b.y));
}

// gather one stage (4 slots x 16x64 fp32, contiguous 16 KB) of W into regs
__device__ __forceinline__ void ldg_stage(float g[16], const float* Ws, int tid) {
    int nt = tid >> 5, tt = tid & 31;
    int kk = nt * 8 + (tt >> 2);
    int c0 = (tt & 3) * 2;
    const float* base = Ws + c0 * 64 + kk;
#pragma unroll
    for (int i = 0; i < 4; i++) {
        const float* p = base + i * 1024;
        g[i*4+0] = p[0];
        g[i*4+1] = p[64];
        g[i*4+2] = p[512];
        g[i*4+3] = p[576];
    }
}
// split + store stage into B-frag layout WF[buf][hl][slot][ntile][lane]
__device__ __forceinline__ void sts_stage(const float g[16], uint2* WF,
                                          int buf, int tid) {
    int nt = tid >> 5, tt = tid & 31;
#pragma unroll
    for (int i = 0; i < 4; i++) {
        uint2 H, L;
        split2(g[i*4+0], g[i*4+1], H.x, L.x);
        split2(g[i*4+2], g[i*4+3], H.y, L.y);
        WF[((buf*2 + 0)*4 + i)*256 + nt*32 + tt] = H;
        WF[((buf*2 + 1)*4 + i)*256 + nt*32 + tt] = L;
    }
}
// build A-fragments (hi/lo) from xk_s fp32 [r][h]
__device__ __forceinline__ void build_xkF(const float* xk_s, uint4* xFH,
                                          uint4* xFL, int tid, int nks) {
    int rg = tid >> 5, tt = tid & 31;
    int tg_ = tt >> 2, c0 = (tt & 3) * 2;
    for (int ks = 0; ks < nks; ks++) {
        const float* p = xk_s + (rg*16 + tg_)*64 + ks*16 + c0;
        float2 v0 = *(const float2*)(p);            // a0: row tg,   k c0
        float2 v1 = *(const float2*)(p + 8*64);     // a1: row tg+8, k c0
        float2 v2 = *(const float2*)(p + 8);        // a2: row tg,   k c0+8
        float2 v3 = *(const float2*)(p + 8*64 + 8); // a3: row tg+8, k c0+8
        uint4 H, L;
        split2(v0.x, v0.y, H.x, L.x);
        split2(v1.x, v1.y, H.y, L.y);
        split2(v2.x, v2.y, H.z, L.z);
        split2(v3.x, v3.y, H.w, L.w);
        xFH[(ks*8 + rg)*32 + tt] = H;
        xFL[(ks*8 + rg)*32 + tt] = L;
    }
}

// one stage = 4 k-slots (MS=1: one m, 4 ksteps; MS=2: two m, 2 ksteps each)
template<int MS>
__device__ __forceinline__ void compute_stage(
    const uint2* WF, const uint4* xFH, const uint4* xFL, const float* x0_s,
    int buf, int s, int wm, int wn, int tg, int lane, float D[2][4][4])
{
    const int KSM = 4 / MS;
    float xs[4];
#pragma unroll
    for (int i = 0; i < 4; i++) {
        const int ksx = (MS == 1) ? i : (i & (KSM - 1));
        const int m = s * MS + i / KSM;
        if (i == 0 || (i % KSM) == 0) {
#pragma unroll
            for (int mt = 0; mt < 2; mt++) {
                int r0 = wm + mt*16 + tg;
                xs[mt*2]   = x0_s[((r0 >> 4) << 9) + m*16 + (r0 & 15)];
                int r1 = r0 + 8;
                xs[mt*2+1] = x0_s[((r1 >> 4) << 9) + m*16 + (r1 & 15)];
            }
        }
        uint4 AH[2], AL[2];
#pragma unroll
        for (int mt = 0; mt < 2; mt++) {
            int rg = (wm >> 4) + mt;
            AH[mt] = xFH[(ksx*8 + rg)*32 + lane];
            AL[mt] = xFL[(ksx*8 + rg)*32 + lane];
        }
#pragma unroll
        for (int nt = 0; nt < 4; nt++) {
            int ntg = (wn >> 3) + nt;
            uint2 BH = WF[((buf*2 + 0)*4 + i)*256 + ntg*32 + lane];
            uint2 BL = WF[((buf*2 + 1)*4 + i)*256 + ntg*32 + lane];
#pragma unroll
            for (int mt = 0; mt < 2; mt++) {
                float P[4];
                mma_zc (P, AH[mt], BH);
                mma_acc(P, AH[mt], BL);
                mma_acc(P, AL[mt], BH);
                D[mt][nt][0] += xs[mt*2]   * P[0];
                D[mt][nt][1] += xs[mt*2]   * P[1];
                D[mt][nt][2] += xs[mt*2+1] * P[2];
                D[mt][nt][3] += xs[mt*2+1] * P[3];
            }
        }
    }
}

template<int MS, bool LAST>
__device__ __forceinline__ void layer(
    const float* Wl, const float* Wnext, int L,
    float* x0_s, float* xk_s, uint4* xFH, uint4* xFL, uint2* WF,
    float* out, long long bg0,
    int tid, int lane, int wm, int wn, int tg, int tc)
{
    const int NS = 32 / MS;
    float D[2][4][4];
#pragma unroll
    for (int mt = 0; mt < 2; mt++)
#pragma unroll
        for (int nt = 0; nt < 4; nt++)
#pragma unroll
            for (int j = 0; j < 4; j++) D[mt][nt][j] = 0.f;

    int buf = 0;
    for (int s = 0; s < NS; s++) {
        float g[16];
        bool pf = (s + 1 < NS);
        if (pf) ldg_stage(g, Wl + (s + 1) * 4096, tid);
        compute_stage<MS>(WF, xFH, xFL, x0_s, buf, s, wm, wn, tg, lane, D);
        if (pf) sts_stage(g, WF, buf ^ 1, tid);
        __syncthreads();
        buf ^= 1;
    }

    // relu + store to xk_s [r][k]
#pragma unroll
    for (int mt = 0; mt < 2; mt++) {
        int r0 = wm + mt*16 + tg;
#pragma unroll
        for (int nt = 0; nt < 4; nt++) {
            int cb = wn + nt*8 + tc*2;
            *(float2*)&xk_s[r0*64 + cb] =
                make_float2(fmaxf(D[mt][nt][0], 0.f), fmaxf(D[mt][nt][1], 0.f));
            *(float2*)&xk_s[(r0 + 8)*64 + cb] =
                make_float2(fmaxf(D[mt][nt][2], 0.f), fmaxf(D[mt][nt][3], 0.f));
        }
    }
    __syncthreads();

    // d-reduce -> out
    {
        int ob = tid >> 5, ok = (tid & 31) * 2;
        float s0 = 0.f, s1 = 0.f;
#pragma unroll
        for (int d = 0; d < 16; d++) {
            float2 v = *(const float2*)&xk_s[(ob*16 + d)*64 + ok];
            s0 += v.x; s1 += v.y;
        }
        *(float2*)&out[(bg0 + ob)*192 + L*64 + ok] = make_float2(s0, s1);
    }
    if (!LAST) {
        build_xkF(xk_s, xFH, xFL, tid, 4);
        float g[16];
        ldg_stage(g, Wnext, tid);
        sts_stage(g, WF, 0, tid);
    }
    __syncthreads();
}

__global__ void __launch_bounds__(THREADS, 2)
cin_kernel(const float* __restrict__ emb,
           const float* __restrict__ W0,
           const float* __restrict__ W1,
           const float* __restrict__ W2,
           float* __restrict__ out)
{
    extern __shared__ char smem[];
    float* x0_s = (float*)(smem + O_X0);
    float* xk_s = (float*)(smem + O_XK);
    uint4* xFH  = (uint4*)(smem + O_XFH);
    uint4* xFL  = (uint4*)(smem + O_XFL);
    uint2* WF   = (uint2*)(smem + O_WF);

    const int tid = threadIdx.x, lane = tid & 31, w = tid >> 5;
    const int wm = (w & 3) * 32;   // warp m-row offset (4 m-warps)
    const int wn = (w >> 2) * 32;  // warp n offset (2 n-warps)
    const int tg = lane >> 2, tc = lane & 3;
    const long long bg0 = (long long)blockIdx.x * TB;

    // load x0 (8 rows x 512 floats, coalesced)
    {
        const float4* g = (const float4*)(emb + bg0 * 512);
        float4* sp = (float4*)x0_s;
#pragma unroll
        for (int i = 0; i < 4; i++) sp[tid + i * THREADS] = g[tid + i * THREADS];
    }
    __syncthreads();
    // xk_s[r][h] = x0[b][h][d], r = b*16+d (h < 32)
#pragma unroll
    for (int i = tid; i < 4096; i += THREADS) {
        int r = i >> 5, h = i & 31;
        xk_s[r*64 + h] = x0_s[((r >> 4) << 9) + h*16 + (r & 15)];
    }
    __syncthreads();
    build_xkF(xk_s, xFH, xFL, tid, 2);
    {
        float g[16];
        ldg_stage(g, W0, tid);
        sts_stage(g, WF, 0, tid);
    }
    __syncthreads();

    layer<2, false>(W0, W1, 0, x0_s, xk_s, xFH, xFL, WF, out, bg0,
                    tid, lane, wm, wn, tg, tc);
    layer<1, false>(W1, W2, 1, x0_s, xk_s, xFH, xFL, WF, out, bg0,
                    tid, lane, wm, wn, tg, tc);
    layer<1, true>(W2, W2, 2, x0_s, xk_s, xFH, xFL, WF, out, bg0,
                   tid, lane, wm, wn, tg, tc);
}

extern "C" void kernel_launch(void* const* d_in, const int* in_sizes, int n_in,
                              void* d_out, int out_size)
{
    const float* emb = (const float*)d_in[0];
    const float* W0  = (const float*)d_in[1];
    const float* W1  = (const float*)d_in[2];
    const float* W2  = (const float*)d_in[3];
    float* out = (float*)d_out;

    cudaFuncSetAttribute(cin_kernel,
                         cudaFuncAttributeMaxDynamicSharedMemorySize, SM_TOTAL);
    cin_kernel<<<16384 / TB, THREADS, SM_TOTAL>>>(emb, W0, W1, W2, out);
}

// round 9
// speedup vs baseline: 3.6881x; 1.2368x over previous
#include <cuda_runtime.h>
#include <cstdint>

// CIN cross-network via warp-level HMMA (mma.sync m16n8k16 bf16, 3-pass
// hi/lo split). A-frags (xk) register-resident per layer; W B-frags
// precomputed once by prep_kernel into WFRAG (L2-resident) and streamed
// per stage via cp.async. Per block: 8 batch rows, r=(b*16+d)=128 x k=64.

#define THREADS 256
#define TB 8

// smem byte offsets
#define O_X0 0         // float[4096]        16 KB
#define O_XK 16384     // float[128*64]      32 KB
#define O_WF 49152     // 2 x 16 KB W-frag stage buffers
#define SM_TOTAL 81920

// 80 stages x 2048 uint2 (16 KB) of pre-split W fragments
__device__ __align__(16) uint2 WFRAG[80 * 2048];

__device__ __forceinline__ uint32_t cvt_bf16x2(float lo, float hi) {
    uint32_t r;
    asm("cvt.rn.satfinite.bf16x2.f32 %0, %1, %2;" : "=r"(r) : "f"(hi), "f"(lo));
    return r;
}
__device__ __forceinline__ void split2(float a, float b, uint32_t& h, uint32_t& l) {
    uint32_t ua = __float_as_uint(a), ub = __float_as_uint(b);
    h = __byte_perm(ua, ub, 0x7632);
    float la = a - __uint_as_float(ua & 0xffff0000u);
    float lb = b - __uint_as_float(ub & 0xffff0000u);
    l = cvt_bf16x2(la, lb);
}
__device__ __forceinline__ void mma_zc(float d[4], const uint4& a, const uint2& b) {
    asm("mma.sync.aligned.m16n8k16.row.col.f32.bf16.bf16.f32 "
        "{%0,%1,%2,%3}, {%4,%5,%6,%7}, {%8,%9}, {%10,%11,%12,%13};"
        : "=f"(d[0]), "=f"(d[1]), "=f"(d[2]), "=f"(d[3])
        : "r"(a.x), "r"(a.y), "r"(a.z), "r"(a.w), "r"(b.x), "r"(b.y),
          "f"(0.f), "f"(0.f), "f"(0.f), "f"(0.f));
}
__device__ __forceinline__ void mma_acc(float d[4], const uint4& a, const uint2& b) {
    asm("mma.sync.aligned.m16n8k16.row.col.f32.bf16.bf16.f32 "
        "{%0,%1,%2,%3}, {%4,%5,%6,%7}, {%8,%9}, {%0,%1,%2,%3};"
        : "+f"(d[0]), "+f"(d[1]), "+f"(d[2]), "+f"(d[3])
        : "r"(a.x), "r"(a.y), "r"(a.z), "r"(a.w), "r"(b.x), "r"(b.y));
}
__device__ __forceinline__ uint32_t smem_u32(const void* p) {
    uint32_t a;
    asm("{ .reg .u64 t; cvta.to.shared.u64 t, %1; cvt.u32.u64 %0, t; }"
        : "=r"(a) : "l"(p));
    return a;
}
__device__ __forceinline__ void cp_async16(uint32_t saddr, const void* gaddr) {
    asm volatile("cp.async.cg.shared.global [%0], [%1], 16;"
                 :: "r"(saddr), "l"(gaddr) : "memory");
}
#define CP_COMMIT() asm volatile("cp.async.commit_group;" ::: "memory")
#define CP_WAIT0()  asm volatile("cp.async.wait_group 0;" ::: "memory")

// ---------- prep: split W into bf16 hi/lo B-fragments, frag layout ----------
// WFRAG[ci][slot][hl][ntg][lane] ; ci 0..79 (L0:0-15, L1:16-47, L2:48-79)
__global__ void prep_kernel(const float* __restrict__ W0,
                            const float* __restrict__ W1,
                            const float* __restrict__ W2)
{
    int t = blockIdx.x * blockDim.x + threadIdx.x;
    if (t >= 80 * 4 * 8 * 32) return;
    int lane = t & 31;
    int ntg  = (t >> 5) & 7;
    int slot = (t >> 8) & 3;
    int ci   = t >> 10;
    const float* Wl; int c;
    if (ci < 16)      { Wl = W0; c = ci; }
    else if (ci < 48) { Wl = W1; c = ci - 16; }
    else              { Wl = W2; c = ci - 48; }
    int kk = ntg * 8 + (lane >> 2);
    int c0 = (lane & 3) * 2;
    const float* p = Wl + c * 4096 + slot * 1024 + c0 * 64 + kk;
    float a0 = p[0], a1 = p[64], a2 = p[512], a3 = p[576];
    uint2 H, L;
    split2(a0, a1, H.x, L.x);
    split2(a2, a3, H.y, L.y);
    WFRAG[ci * 2048 + (slot * 2 + 0) * 256 + ntg * 32 + lane] = H;
    WFRAG[ci * 2048 + (slot * 2 + 1) * 256 + ntg * 32 + lane] = L;
}

// ---------- main ----------
// build register A-frags from xk_s [r][64]
template<int NKS>
__device__ __forceinline__ void build_A(const float* xk_s, uint4 AH[4][2],
                                        uint4 AL[4][2], int wm, int tg, int c0)
{
#pragma unroll
    for (int ks = 0; ks < NKS; ks++)
#pragma unroll
        for (int mt = 0; mt < 2; mt++) {
            const float* p = xk_s + (wm + mt * 16 + tg) * 64 + ks * 16 + c0;
            float2 v0 = *(const float2*)(p);
            float2 v1 = *(const float2*)(p + 8 * 64);
            float2 v2 = *(const float2*)(p + 8);
            float2 v3 = *(const float2*)(p + 8 * 64 + 8);
            uint4 H, L;
            split2(v0.x, v0.y, H.x, L.x);
            split2(v1.x, v1.y, H.y, L.y);
            split2(v2.x, v2.y, H.z, L.z);
            split2(v3.x, v3.y, H.w, L.w);
            AH[ks][mt] = H; AL[ks][mt] = L;
        }
}

template<int MS>
__device__ __forceinline__ void compute_stage(
    const uint2* __restrict__ WFb, const uint4 AH[4][2], const uint4 AL[4][2],
    const float* x0_s, int s, int wm, int wn, int tg, int lane, float D[2][4][4])
{
    const int KSM = 4 / MS;
    float xs[4];
#pragma unroll
    for (int i = 0; i < 4; i++) {
        const int ksx = (MS == 1) ? i : (i & (KSM - 1));
        const int m = s * MS + i / KSM;
        if ((i % KSM) == 0) {
#pragma unroll
            for (int mt = 0; mt < 2; mt++) {
                int r0 = wm + mt * 16 + tg;
                xs[mt * 2]     = x0_s[((r0 >> 4) << 9) + m * 16 + (r0 & 15)];
                int r1 = r0 + 8;
                xs[mt * 2 + 1] = x0_s[((r1 >> 4) << 9) + m * 16 + (r1 & 15)];
            }
        }
#pragma unroll
        for (int nt = 0; nt < 4; nt++) {
            int ntg = (wn >> 3) + nt;
            uint2 BH = WFb[(i * 2 + 0) * 256 + ntg * 32 + lane];
            uint2 BL = WFb[(i * 2 + 1) * 256 + ntg * 32 + lane];
#pragma unroll
            for (int mt = 0; mt < 2; mt++) {
                float P[4];
                mma_zc (P, AH[ksx][mt], BH);
                mma_acc(P, AH[ksx][mt], BL);
                mma_acc(P, AL[ksx][mt], BH);
                D[mt][nt][0] += xs[mt * 2]     * P[0];
                D[mt][nt][1] += xs[mt * 2]     * P[1];
                D[mt][nt][2] += xs[mt * 2 + 1] * P[2];
                D[mt][nt][3] += xs[mt * 2 + 1] * P[3];
            }
        }
    }
}

__device__ __forceinline__ void fetch_stage(uint32_t sdst, int ci, int tid) {
#pragma unroll
    for (int q = 0; q < 4; q++) {
        int off = (q * 256 + tid) * 16;
        cp_async16(sdst + off, (const char*)WFRAG + (size_t)ci * 16384 + off);
    }
    CP_COMMIT();
}

template<int MS, bool LAST>
__device__ __forceinline__ void layer(
    int ci0, int L,
    float* x0_s, float* xk_s, uint2* WFs, uint32_t wf_sm,
    uint4 AH[4][2], uint4 AL[4][2],
    float* out, long long bg0,
    int tid, int lane, int wm, int wn, int tg, int tc)
{
    const int NS = (MS == 2) ? 16 : 32;
    float D[2][4][4];
#pragma unroll
    for (int mt = 0; mt < 2; mt++)
#pragma unroll
        for (int nt = 0; nt < 4; nt++)
#pragma unroll
            for (int j = 0; j < 4; j++) D[mt][nt][j] = 0.f;

    int buf = 0;
    for (int s = 0; s < NS; s++) {
        if (s + 1 < NS)      fetch_stage(wf_sm + (buf ^ 1) * 16384, ci0 + s + 1, tid);
        else if (!LAST)      fetch_stage(wf_sm + (buf ^ 1) * 16384, ci0 + NS, tid);
        compute_stage<MS>(WFs + buf * 2048, AH, AL, x0_s, s, wm, wn, tg, lane, D);
        CP_WAIT0();
        __syncthreads();
        buf ^= 1;
    }

    // relu -> xk_s [r][k]
#pragma unroll
    for (int mt = 0; mt < 2; mt++) {
        int r0 = wm + mt * 16 + tg;
#pragma unroll
        for (int nt = 0; nt < 4; nt++) {
            int cb = wn + nt * 8 + tc * 2;
            *(float2*)&xk_s[r0 * 64 + cb] =
                make_float2(fmaxf(D[mt][nt][0], 0.f), fmaxf(D[mt][nt][1], 0.f));
            *(float2*)&xk_s[(r0 + 8) * 64 + cb] =
                make_float2(fmaxf(D[mt][nt][2], 0.f), fmaxf(D[mt][nt][3], 0.f));
        }
    }
    __syncthreads();

    // d-reduce -> out
    {
        int ob = tid >> 5, ok = (tid & 31) * 2;
        float s0 = 0.f, s1 = 0.f;
#pragma unroll
        for (int d = 0; d < 16; d++) {
            float2 v = *(const float2*)&xk_s[(ob * 16 + d) * 64 + ok];
            s0 += v.x; s1 += v.y;
        }
        *(float2*)&out[(bg0 + ob) * 192 + L * 64 + ok] = make_float2(s0, s1);
    }
    if (!LAST) {
        int c0 = (lane & 3) * 2;
        build_A<4>(xk_s, AH, AL, wm, tg, c0);
    }
    __syncthreads();
}

__global__ void __launch_bounds__(THREADS, 2)
cin_kernel(const float* __restrict__ emb,
           const float* __restrict__ W0,
           const float* __restrict__ W1,
           const float* __restrict__ W2,
           float* __restrict__ out)
{
    extern __shared__ char smem[];
    float* x0_s = (float*)(smem + O_X0);
    float* xk_s = (float*)(smem + O_XK);
    uint2* WFs  = (uint2*)(smem + O_WF);
    const uint32_t wf_sm = smem_u32(smem + O_WF);

    const int tid = threadIdx.x, lane = tid & 31, w = tid >> 5;
    const int wm = (w & 3) * 32;
    const int wn = (w >> 2) * 32;
    const int tg = lane >> 2, tc = lane & 3;
    const int c0 = tc * 2;
    const long long bg0 = (long long)blockIdx.x * TB;

    // load x0 (coalesced)
    {
        const float4* g = (const float4*)(emb + bg0 * 512);
        float4* sp = (float4*)x0_s;
#pragma unroll
        for (int i = 0; i < 4; i++) sp[tid + i * THREADS] = g[tid + i * THREADS];
    }
    // prefetch stage 0
    fetch_stage(wf_sm, 0, tid);
    __syncthreads();
    // xk_s[r][h] = x0[b][h][d], r = b*16+d (h < 32)
#pragma unroll
    for (int i = tid; i < 4096; i += THREADS) {
        int r = i >> 5, h = i & 31;
        xk_s[r * 64 + h] = x0_s[((r >> 4) << 9) + h * 16 + (r & 15)];
    }
    CP_WAIT0();
    __syncthreads();

    uint4 AH[4][2], AL[4][2];
    build_A<2>(xk_s, AH, AL, wm, tg, c0);

    layer<2, false>(0,  0, x0_s, xk_s, WFs, wf_sm, AH, AL, out, bg0,
                    tid, lane, wm, wn, tg, tc);
    layer<1, false>(16, 1, x0_s, xk_s, WFs, wf_sm, AH, AL, out, bg0,
                    tid, lane, wm, wn, tg, tc);
    layer<1, true >(48, 2, x0_s, xk_s, WFs, wf_sm, AH, AL, out, bg0,
                    tid, lane, wm, wn, tg, tc);
}

extern "C" void kernel_launch(void* const* d_in, const int* in_sizes, int n_in,
                              void* d_out, int out_size)
{
    const float* emb = (const float*)d_in[0];
    const float* W0  = (const float*)d_in[1];
    const float* W1  = (const float*)d_in[2];
    const float* W2  = (const float*)d_in[3];
    float* out = (float*)d_out;

    prep_kernel<<<320, 256>>>(W0, W1, W2);
    cudaFuncSetAttribute(cin_kernel,
                         cudaFuncAttributeMaxDynamicSharedMemorySize, SM_TOTAL);
    cin_kernel<<<16384 / TB, THREADS, SM_TOTAL>>>(emb, W0, W1, W2, out);
}

// round 10
// speedup vs baseline: 4.0024x; 1.0852x over previous
#include <cuda_runtime.h>
#include <cstdint>

// CIN cross-network via warp-level HMMA (mma.sync m16n8k16 bf16, 3-pass
// hi/lo split). Warp = 16 rows x 64 cols. A-frags register-resident;
// W B-frags precomputed by prep_kernel into WFRAG and streamed via
// cp.async in 32 KB stages (40 barriers total). P chained in the MMA
// accumulator across the k-steps of each m; one fp32 fold per m.

#define THREADS 256
#define TB 8

// smem byte offsets
#define O_X0 0         // float[4096]        16 KB
#define O_XK 16384     // float[128*64]      32 KB
#define O_WF 49152     // 2 x 32 KB W-frag stage buffers
#define SM_TOTAL 114688

// 80 chunks x 2048 uint2 (16 KB) of pre-split W fragments
__device__ __align__(16) uint2 WFRAG[80 * 2048];

__device__ __forceinline__ uint32_t cvt_bf16x2(float lo, float hi) {
    uint32_t r;
    asm("cvt.rn.satfinite.bf16x2.f32 %0, %1, %2;" : "=r"(r) : "f"(hi), "f"(lo));
    return r;
}
__device__ __forceinline__ void split2(float a, float b, uint32_t& h, uint32_t& l) {
    uint32_t ua = __float_as_uint(a), ub = __float_as_uint(b);
    h = __byte_perm(ua, ub, 0x7632);
    float la = a - __uint_as_float(ua & 0xffff0000u);
    float lb = b - __uint_as_float(ub & 0xffff0000u);
    l = cvt_bf16x2(la, lb);
}
__device__ __forceinline__ void mma_zc(float d[4], const uint4& a, const uint2& b) {
    asm("mma.sync.aligned.m16n8k16.row.col.f32.bf16.bf16.f32 "
        "{%0,%1,%2,%3}, {%4,%5,%6,%7}, {%8,%9}, {%10,%11,%12,%13};"
        : "=f"(d[0]), "=f"(d[1]), "=f"(d[2]), "=f"(d[3])
        : "r"(a.x), "r"(a.y), "r"(a.z), "r"(a.w), "r"(b.x), "r"(b.y),
          "f"(0.f), "f"(0.f), "f"(0.f), "f"(0.f));
}
__device__ __forceinline__ void mma_acc(float d[4], const uint4& a, const uint2& b) {
    asm("mma.sync.aligned.m16n8k16.row.col.f32.bf16.bf16.f32 "
        "{%0,%1,%2,%3}, {%4,%5,%6,%7}, {%8,%9}, {%0,%1,%2,%3};"
        : "+f"(d[0]), "+f"(d[1]), "+f"(d[2]), "+f"(d[3])
        : "r"(a.x), "r"(a.y), "r"(a.z), "r"(a.w), "r"(b.x), "r"(b.y));
}
__device__ __forceinline__ uint32_t smem_u32(const void* p) {
    uint32_t a;
    asm("{ .reg .u64 t; cvta.to.shared.u64 t, %1; cvt.u32.u64 %0, t; }"
        : "=r"(a) : "l"(p));
    return a;
}
__device__ __forceinline__ void cp_async16(uint32_t saddr, const void* gaddr) {
    asm volatile("cp.async.cg.shared.global [%0], [%1], 16;"
                 :: "r"(saddr), "l"(gaddr) : "memory");
}
#define CP_COMMIT() asm volatile("cp.async.commit_group;" ::: "memory")
#define CP_WAIT0()  asm volatile("cp.async.wait_group 0;" ::: "memory")

// ---------- prep: split W into bf16 hi/lo B-fragments ----------
// WFRAG[ci][slot][hl][ntg][lane] ; ci 0..79 (L0:0-15, L1:16-47, L2:48-79)
__global__ void prep_kernel(const float* __restrict__ W0,
                            const float* __restrict__ W1,
                            const float* __restrict__ W2)
{
    int t = blockIdx.x * blockDim.x + threadIdx.x;
    if (t >= 80 * 4 * 8 * 32) return;
    int lane = t & 31;
    int ntg  = (t >> 5) & 7;
    int slot = (t >> 8) & 3;
    int ci   = t >> 10;
    const float* Wl; int c;
    if (ci < 16)      { Wl = W0; c = ci; }
    else if (ci < 48) { Wl = W1; c = ci - 16; }
    else              { Wl = W2; c = ci - 48; }
    int kk = ntg * 8 + (lane >> 2);
    int c0 = (lane & 3) * 2;
    const float* p = Wl + c * 4096 + slot * 1024 + c0 * 64 + kk;
    float a0 = p[0], a1 = p[64], a2 = p[512], a3 = p[576];
    uint2 H, L;
    split2(a0, a1, H.x, L.x);
    split2(a2, a3, H.y, L.y);
    WFRAG[ci * 2048 + (slot * 2 + 0) * 256 + ntg * 32 + lane] = H;
    WFRAG[ci * 2048 + (slot * 2 + 1) * 256 + ntg * 32 + lane] = L;
}

// ---------- main ----------
// build register A-frags from xk_s [r][64] for this warp's 16 rows
template<int NKS>
__device__ __forceinline__ void build_A(const float* xk_s, uint4 AH[4],
                                        uint4 AL[4], int wm, int tg, int c0)
{
#pragma unroll
    for (int ks = 0; ks < NKS; ks++) {
        const float* p = xk_s + (wm + tg) * 64 + ks * 16 + c0;
        float2 v0 = *(const float2*)(p);
        float2 v1 = *(const float2*)(p + 8 * 64);
        float2 v2 = *(const float2*)(p + 8);
        float2 v3 = *(const float2*)(p + 8 * 64 + 8);
        uint4 H, L;
        split2(v0.x, v0.y, H.x, L.x);
        split2(v1.x, v1.y, H.y, L.y);
        split2(v2.x, v2.y, H.z, L.z);
        split2(v3.x, v3.y, H.w, L.w);
        AH[ks] = H; AL[ks] = L;
    }
}

// one 32 KB stage = 8 k-slots = 8/KSM m-values (KSM = k-steps per m)
template<int KSM>
__device__ __forceinline__ void compute_stage(
    const uint2* __restrict__ WFb, const uint4 AH[4], const uint4 AL[4],
    const float* x0_s, int s, int w, int tg, int lane, float D[8][4])
{
    const int MPS = 8 / KSM;
#pragma unroll
    for (int mm = 0; mm < MPS; mm++) {
        const int m = s * MPS + mm;
        float xs0 = x0_s[w * 512 + m * 16 + tg];
        float xs1 = x0_s[w * 512 + m * 16 + tg + 8];
        float P[8][4];
#pragma unroll
        for (int i = 0; i < KSM; i++) {
            const int si = mm * KSM + i;
#pragma unroll
            for (int nt = 0; nt < 8; nt++) {
                uint2 BH = WFb[(si * 2 + 0) * 256 + nt * 32 + lane];
                uint2 BL = WFb[(si * 2 + 1) * 256 + nt * 32 + lane];
                if (i == 0) mma_zc(P[nt], AH[i], BH);
                else        mma_acc(P[nt], AH[i], BH);
                mma_acc(P[nt], AH[i], BL);
                mma_acc(P[nt], AL[i], BH);
            }
        }
#pragma unroll
        for (int nt = 0; nt < 8; nt++) {
            D[nt][0] += xs0 * P[nt][0];
            D[nt][1] += xs0 * P[nt][1];
            D[nt][2] += xs1 * P[nt][2];
            D[nt][3] += xs1 * P[nt][3];
        }
    }
}

// fetch one 32 KB stage (2 consecutive 16 KB chunks) via cp.async
__device__ __forceinline__ void fetch_stage(uint32_t sdst, int ci, int tid) {
#pragma unroll
    for (int q = 0; q < 8; q++) {
        int off = (q * 256 + tid) * 16;
        cp_async16(sdst + off, (const char*)WFRAG + (size_t)ci * 16384 + off);
    }
    CP_COMMIT();
}

template<int KSM, bool LAST>
__device__ __forceinline__ void layer(
    int ci0, int nextci0, int L,
    float* x0_s, float* xk_s, uint2* WFs, uint32_t wf_sm,
    uint4 AH[4], uint4 AL[4],
    float* out, long long bg0,
    int tid, int lane, int wm, int w, int tg, int tc)
{
    const int NS = (KSM == 2) ? 8 : 16;   // stages this layer
    float D[8][4];
#pragma unroll
    for (int nt = 0; nt < 8; nt++)
#pragma unroll
        for (int j = 0; j < 4; j++) D[nt][j] = 0.f;

    int buf = 0;
    for (int s = 0; s < NS; s++) {
        if (s + 1 < NS) fetch_stage(wf_sm + (buf ^ 1) * 32768, ci0 + 2 * (s + 1), tid);
        else if (!LAST) fetch_stage(wf_sm + (buf ^ 1) * 32768, nextci0, tid);
        compute_stage<KSM>(WFs + buf * 4096, AH, AL, x0_s, s, w, tg, lane, D);
        CP_WAIT0();
        __syncthreads();
        buf ^= 1;
    }

    // relu -> xk_s [r][k]
    {
        int r0 = wm + tg;
#pragma unroll
        for (int nt = 0; nt < 8; nt++) {
            int cb = nt * 8 + tc * 2;
            *(float2*)&xk_s[r0 * 64 + cb] =
                make_float2(fmaxf(D[nt][0], 0.f), fmaxf(D[nt][1], 0.f));
            *(float2*)&xk_s[(r0 + 8) * 64 + cb] =
                make_float2(fmaxf(D[nt][2], 0.f), fmaxf(D[nt][3], 0.f));
        }
    }
    __syncthreads();

    // d-reduce -> out
    {
        int ob = tid >> 5, ok = (tid & 31) * 2;
        float s0 = 0.f, s1 = 0.f;
#pragma unroll
        for (int d = 0; d < 16; d++) {
            float2 v = *(const float2*)&xk_s[(ob * 16 + d) * 64 + ok];
            s0 += v.x; s1 += v.y;
        }
        *(float2*)&out[(bg0 + ob) * 192 + L * 64 + ok] = make_float2(s0, s1);
    }
    if (!LAST) {
        int c0 = tc * 2;
        build_A<4>(xk_s, AH, AL, wm, tg, c0);
    }
    __syncthreads();
}

__global__ void __launch_bounds__(THREADS, 2)
cin_kernel(const float* __restrict__ emb,
           const float* __restrict__ W0,
           const float* __restrict__ W1,
           const float* __restrict__ W2,
           float* __restrict__ out)
{
    extern __shared__ char smem[];
    float* x0_s = (float*)(smem + O_X0);
    float* xk_s = (float*)(smem + O_XK);
    uint2* WFs  = (uint2*)(smem + O_WF);
    const uint32_t wf_sm = smem_u32(smem + O_WF);

    const int tid = threadIdx.x, lane = tid & 31, w = tid >> 5;
    const int wm = w * 16;        // warp owns rows wm..wm+15, all 64 cols
    const int tg = lane >> 2, tc = lane & 3;
    const int c0 = tc * 2;
    const long long bg0 = (long long)blockIdx.x * TB;

    // load x0 (coalesced)
    {
        const float4* g = (const float4*)(emb + bg0 * 512);
        float4* sp = (float4*)x0_s;
#pragma unroll
        for (int i = 0; i < 4; i++) sp[tid + i * THREADS] = g[tid + i * THREADS];
    }
    // prefetch stage 0 (chunks 0,1)
    fetch_stage(wf_sm, 0, tid);
    __syncthreads();
    // xk_s[r][h] = x0[b][h][d], r = b*16+d (h < 32)
#pragma unroll
    for (int i = tid; i < 4096; i += THREADS) {
        int r = i >> 5, h = i & 31;
        xk_s[r * 64 + h] = x0_s[((r >> 4) << 9) + h * 16 + (r & 15)];
    }
    CP_WAIT0();
    __syncthreads();

    uint4 AH[4], AL[4];
    build_A<2>(xk_s, AH, AL, wm, tg, c0);

    layer<2, false>(0,  16, 0, x0_s, xk_s, WFs, wf_sm, AH, AL, out, bg0,
                    tid, lane, wm, w, tg, tc);
    layer<4, false>(16, 48, 1, x0_s, xk_s, WFs, wf_sm, AH, AL, out, bg0,
                    tid, lane, wm, w, tg, tc);
    layer<4, true >(48, 0,  2, x0_s, xk_s, WFs, wf_sm, AH, AL, out, bg0,
                    tid, lane, wm, w, tg, tc);
}

extern "C" void kernel_launch(void* const* d_in, const int* in_sizes, int n_in,
                              void* d_out, int out_size)
{
    const float* emb = (const float*)d_in[0];
    const float* W0  = (const float*)d_in[1];
    const float* W1  = (const float*)d_in[2];
    const float* W2  = (const float*)d_in[3];
    float* out = (float*)d_out;

    prep_kernel<<<320, 256>>>(W0, W1, W2);
    cudaFuncSetAttribute(cin_kernel,
                         cudaFuncAttributeMaxDynamicSharedMemorySize, SM_TOTAL);
    cin_kernel<<<16384 / TB, THREADS, SM_TOTAL>>>(emb, W0, W1, W2, out);
}